// round 15
// baseline (speedup 1.0000x reference)
#include <cuda_runtime.h>
#include <cuda_fp16.h>
#include <math.h>
#include <stdint.h>

// Problem constants
#define NMAX   20000
#define EMAX   320000
#define GDIM   256
#define HIDDIM 512
#define KBIG   4096
#define QKVW   768
#define EPSLN  1e-5f
#define SCALE  0.0625f

// ---------------- scratch (static device globals) ---------------------------
__device__ __align__(256) float g_xp  [NMAX * GDIM];
__device__ __align__(256) float g_hn  [NMAX * GDIM];
__device__ __align__(256) float g_attn[NMAX * GDIM];

__device__ int g_deg [NMAX];
__device__ int g_off [NMAX + 1];
__device__ int g_rank[EMAX];
__device__ int g_ssrc[EMAX];

// fp16 operands
__device__ __align__(256) __half g_qkvh[NMAX * QKVW];
__device__ __align__(256) __half g_cwhi[GDIM * KBIG];
__device__ __align__(256) __half g_shi [NMAX * GDIM];
__device__ __align__(256) __half g_qwhi[QKVW * GDIM];
__device__ __align__(256) __half g_rsthi[NMAX * GDIM];
__device__ __align__(256) __half g_owhi[GDIM * GDIM];
__device__ __align__(256) __half g_fhi [NMAX * GDIM];
__device__ __align__(256) __half g_w1hi[HIDDIM * GDIM];
__device__ __align__(256) __half g_ghi [NMAX * HIDDIM];
__device__ __align__(256) __half g_w2hi[GDIM * HIDDIM];

// ---------------- PTX helpers -------------------------------------------------
__device__ __forceinline__ uint32_t smem_u32(const void* p) {
    uint32_t a;
    asm("{ .reg .u64 t; cvta.to.shared.u64 t, %1; cvt.u32.u64 %0, t; }"
        : "=r"(a) : "l"(p));
    return a;
}
__device__ __forceinline__ void cpasync16(uint32_t dst, const void* src, int bytes) {
    asm volatile("cp.async.cg.shared.global [%0], [%1], 16, %2;"
                 :: "r"(dst), "l"(src), "r"(bytes));
}
__device__ __forceinline__ void cp_commit() { asm volatile("cp.async.commit_group;" ::: "memory"); }

__device__ __forceinline__ void ldm4(uint32_t r[4], uint32_t addr) {
    asm volatile("ldmatrix.sync.aligned.m8n8.x4.shared.b16 {%0,%1,%2,%3}, [%4];"
                 : "=r"(r[0]), "=r"(r[1]), "=r"(r[2]), "=r"(r[3]) : "r"(addr));
}
__device__ __forceinline__ void mma16816(float c[4], const uint32_t a[4], const uint32_t b[2]) {
    asm volatile("mma.sync.aligned.m16n8k16.row.col.f32.f16.f16.f32 "
                 "{%0,%1,%2,%3}, {%4,%5,%6,%7}, {%8,%9}, {%0,%1,%2,%3};"
                 : "+f"(c[0]), "+f"(c[1]), "+f"(c[2]), "+f"(c[3])
                 : "r"(a[0]), "r"(a[1]), "r"(a[2]), "r"(a[3]), "r"(b[0]), "r"(b[1]));
}

// ---------------- 1-term fp16 mma.sync GEMM --------------------------------------
// C[M,Nn] = Ahi[M,K] @ Whi[Nn,K]^T (+bias)(+epilogue); 1 MMA per tile step.
// EPI: 0 = fp32 store, 1 = GELU -> fp16, 2 = +add1+add2 fp32, 3 = plain fp16
#define RSTRIDE   80
#define ARR_BYTES 10240
#define AFP_ROW   144

template <int EPI, int FUSEA, int NST>
__global__ void __launch_bounds__(256, 2) gemm_mma(
        const float* __restrict__ Afp,
        const __half* __restrict__ Ahi,
        const __half* __restrict__ Whi,
        const float* __restrict__ bias,
        const float* __restrict__ add1, const float* __restrict__ add2,
        float* __restrict__ Cf, __half* __restrict__ Chi,
        int M, int Nn, int K) {
    constexpr int AFPB = FUSEA ? (128 * AFP_ROW) : 0;
    constexpr int STB  = AFPB + 2 * ARR_BYTES;
    constexpr int WOFF = AFPB + ARR_BYTES;

    extern __shared__ char smem[];
    uint32_t sb = smem_u32(smem);
    const int tid    = threadIdx.x;
    const int wid    = tid >> 5;
    const int lane   = tid & 31;
    const int warp_m = wid & 3;
    const int warp_n = wid >> 2;
    const int bm = blockIdx.y * 128;
    const int bn = blockIdx.x * 128;

    const size_t Krow2 = (size_t)K * 2;

    auto load_stage = [&](int s, int c) {
        uint32_t base = sb + s * STB;
        if (FUSEA) {
#pragma unroll
            for (int i = 0; i < 4; i++) {
                int u = tid + i * 256;
                int row = u >> 3, seg = u & 7;
                int ga = bm + row;
                bool ok = ga < M;
                const char* src = (const char*)Afp + (size_t)(ok ? ga : 0) * K * 4
                                  + (size_t)c * 128 + seg * 16;
                cpasync16(base + row * AFP_ROW + seg * 16, src, ok ? 16 : 0);
            }
        } else {
            size_t kb = (size_t)c * 64;
#pragma unroll
            for (int i = 0; i < 2; i++) {
                int u = tid + i * 256;
                int row = u >> 2, seg = u & 3;
                uint32_t so = (uint32_t)(row * RSTRIDE + seg * 16);
                int ga = bm + row;
                bool ok = ga < M;
                size_t go = (size_t)(ok ? ga : 0) * Krow2 + kb + seg * 16;
                cpasync16(base + AFPB + so, (const char*)Ahi + go, ok ? 16 : 0);
            }
        }
        {
            size_t kb = (size_t)c * 64;
#pragma unroll
            for (int i = 0; i < 2; i++) {
                int u = tid + i * 256;
                int row = u >> 2, seg = u & 3;
                uint32_t so = (uint32_t)(row * RSTRIDE + seg * 16);
                size_t gw = (size_t)(bn + row) * Krow2 + kb + seg * 16;
                cpasync16(base + WOFF + so, (const char*)Whi + gw, 16);
            }
        }
        cp_commit();
    };

    const int nc = K >> 5;
#pragma unroll
    for (int s = 0; s < NST; s++) load_stage(s, s);

    float acc[2][8][4];
#pragma unroll
    for (int i = 0; i < 2; i++)
#pragma unroll
        for (int j = 0; j < 8; j++)
#pragma unroll
            for (int q = 0; q < 4; q++) acc[i][j][q] = 0.f;

    for (int c = 0; c < nc; c++) {
        int s = c % NST;
        int allow = min(nc, c + NST) - c - 1;
        if (allow >= 2)      asm volatile("cp.async.wait_group 2;" ::: "memory");
        else if (allow == 1) asm volatile("cp.async.wait_group 1;" ::: "memory");
        else                 asm volatile("cp.async.wait_group 0;" ::: "memory");
        __syncthreads();

        char* stg = smem + s * STB;
        if (FUSEA) {
#pragma unroll
            for (int j = 0; j < 16; j++) {
                int idx = j * 256 + tid;
                int row = idx >> 5, col = idx & 31;
                float f = *(const float*)(stg + row * AFP_ROW + col * 4);
                *(__half*)(stg + AFPB + row * RSTRIDE + col * 2) = __float2half_rn(f);
            }
            __syncthreads();
        }

        uint32_t AhiB = sb + s * STB + AFPB;
#pragma unroll
        for (int ks = 0; ks < 2; ks++) {
            uint32_t a_hi[2][4];
#pragma unroll
            for (int fm = 0; fm < 2; fm++) {
                uint32_t ar = AhiB + (uint32_t)((warp_m * 32 + fm * 16 + (lane & 15)) * RSTRIDE)
                              + ks * 32 + ((lane >> 4) << 4);
                ldm4(a_hi[fm], ar);
            }
            uint32_t b_hi[8][2];
#pragma unroll
            for (int fp = 0; fp < 4; fp++) {
                uint32_t br = sb + s * STB + WOFF
                              + (uint32_t)((warp_n * 64 + fp * 16 + ((lane >> 4) << 3) + (lane & 7)) * RSTRIDE)
                              + ks * 32 + (((lane >> 3) & 1) << 4);
                uint32_t t[4];
                ldm4(t, br);
                b_hi[2 * fp][0] = t[0]; b_hi[2 * fp][1] = t[1];
                b_hi[2 * fp + 1][0] = t[2]; b_hi[2 * fp + 1][1] = t[3];
            }
#pragma unroll
            for (int fm = 0; fm < 2; fm++)
#pragma unroll
                for (int fn = 0; fn < 8; fn++)
                    mma16816(acc[fm][fn], a_hi[fm], b_hi[fn]);
        }
        __syncthreads();
        if (c + NST < nc) load_stage(s, c + NST);
    }

    // epilogue
#pragma unroll
    for (int fm = 0; fm < 2; fm++) {
        int r0 = bm + warp_m * 32 + fm * 16 + (lane >> 2);
#pragma unroll
        for (int half = 0; half < 2; half++) {
            int row = r0 + half * 8;
            if (row >= M) continue;
#pragma unroll
            for (int fn = 0; fn < 8; fn++) {
                int col = bn + warp_n * 64 + fn * 8 + (lane & 3) * 2;
                float v0 = acc[fm][fn][half * 2 + 0];
                float v1 = acc[fm][fn][half * 2 + 1];
                if (bias) { v0 += bias[col]; v1 += bias[col + 1]; }
                size_t ob = (size_t)row * Nn + col;
                if (EPI == 0) {
                    *(float2*)(Cf + ob) = make_float2(v0, v1);
                } else if (EPI == 1) {
                    float u0 = 0.5f * v0 * (1.0f + erff(v0 * 0.70710678118654752f));
                    float u1 = 0.5f * v1 * (1.0f + erff(v1 * 0.70710678118654752f));
                    *(__half2*)(Chi + ob) = __floats2half2_rn(u0, u1);
                } else if (EPI == 2) {
                    float2 a1 = *(const float2*)(add1 + ob);
                    float2 a2 = *(const float2*)(add2 + ob);
                    *(float2*)(Cf + ob) = make_float2(v0 + a1.x + a2.x, v1 + a1.y + a2.y);
                } else {
                    *(__half2*)(Chi + ob) = __floats2half2_rn(v0, v1);
                }
            }
        }
    }
}

// ---------------- fp32 -> fp16 convert --------------------------------------------
__global__ void cvt_hi_k(const float* __restrict__ src, __half* __restrict__ hi, int n4) {
    int i = blockIdx.x * blockDim.x + threadIdx.x;
    if (i >= n4) return;
    float4 v = ((const float4*)src)[i];
    ((__half2*)hi)[2 * i]     = __floats2half2_rn(v.x, v.y);
    ((__half2*)hi)[2 * i + 1] = __floats2half2_rn(v.z, v.w);
}

// ---------------- LayerNorm helpers ---------------------------------------------
__device__ __forceinline__ float wredsum(float v) {
#pragma unroll
    for (int o = 16; o > 0; o >>= 1) v += __shfl_xor_sync(0xffffffffu, v, o);
    return v;
}
__device__ __forceinline__ void ln_row(float v[8], int lane,
                                       const float* __restrict__ w,
                                       const float* __restrict__ b, float o[8]) {
    float sum = 0.f;
#pragma unroll
    for (int j = 0; j < 8; j++) sum += v[j];
    sum = wredsum(sum);
    float mu = sum * (1.0f / 256.0f);
    float sq = 0.f;
#pragma unroll
    for (int j = 0; j < 8; j++) { float d = v[j] - mu; sq += d * d; }
    sq = wredsum(sq);
    float rs = rsqrtf(sq * (1.0f / 256.0f) + EPSLN);
#pragma unroll
    for (int j = 0; j < 8; j++) {
        int i = lane + 32 * j;
        o[j] = (v[j] - mu) * rs * w[i] + b[i];
    }
}

__global__ void double_ln_kernel(const float* __restrict__ h,
                                 const float* __restrict__ nw, const float* __restrict__ nb,
                                 const float* __restrict__ iw, const float* __restrict__ ib,
                                 float* __restrict__ hn,
                                 __half* __restrict__ shi, int M) {
    int row  = blockIdx.x * (blockDim.x >> 5) + (threadIdx.x >> 5);
    int lane = threadIdx.x & 31;
    if (row >= M) return;
    const float* r = h + (size_t)row * 256;
    float v[8], o1[8], o2[8];
#pragma unroll
    for (int j = 0; j < 8; j++) v[j] = r[lane + 32 * j];
    ln_row(v, lane, nw, nb, o1);
#pragma unroll
    for (int j = 0; j < 8; j++) hn[(size_t)row * 256 + lane + 32 * j] = o1[j];
    ln_row(o1, lane, iw, ib, o2);
#pragma unroll
    for (int j = 0; j < 8; j++)
        shi[(size_t)row * 256 + lane + 32 * j] = __float2half_rn(o2[j]);
}

__global__ void ln_hi_kernel(const float* __restrict__ in,
                             const float* __restrict__ w, const float* __restrict__ b,
                             __half* __restrict__ fhi, int M) {
    int row  = blockIdx.x * (blockDim.x >> 5) + (threadIdx.x >> 5);
    int lane = threadIdx.x & 31;
    if (row >= M) return;
    const float* r = in + (size_t)row * 256;
    float v[8], o[8];
#pragma unroll
    for (int j = 0; j < 8; j++) v[j] = r[lane + 32 * j];
    ln_row(v, lane, w, b, o);
#pragma unroll
    for (int j = 0; j < 8; j++)
        fhi[(size_t)row * 256 + lane + 32 * j] = __float2half_rn(o[j]);
}

// ---------------- CSR build ------------------------------------------------------
__global__ void zero_deg_kernel(int M) {
    int i = blockIdx.x * blockDim.x + threadIdx.x;
    if (i < M) g_deg[i] = 0;
}
__global__ void count_kernel(const int* __restrict__ dst, int E) {
    int e = blockIdx.x * blockDim.x + threadIdx.x;
    if (e >= E) return;
    g_rank[e] = atomicAdd(&g_deg[dst[e]], 1);
}
__global__ void scan_kernel(int M, int E) {
    __shared__ int a[1024], b[1024];
    __shared__ int carry;
    int tid = threadIdx.x;
    if (tid == 0) carry = 0;
    __syncthreads();
    for (int base = 0; base < M; base += 1024) {
        int i = base + tid;
        int v = (i < M) ? g_deg[i] : 0;
        a[tid] = v;
        __syncthreads();
        int* s = a; int* d = b;
#pragma unroll
        for (int o = 1; o < 1024; o <<= 1) {
            int t = s[tid] + ((tid >= o) ? s[tid - o] : 0);
            d[tid] = t;
            __syncthreads();
            int* tmp = s; s = d; d = tmp;
        }
        if (i < M) g_off[i] = carry + s[tid] - v;
        int total = s[1023];
        __syncthreads();
        if (tid == 0) carry += total;
        __syncthreads();
    }
    if (tid == 0) g_off[M] = E;
}
__global__ void scatter_kernel(const int* __restrict__ src, const int* __restrict__ dst, int E) {
    int e = blockIdx.x * blockDim.x + threadIdx.x;
    if (e >= E) return;
    g_ssrc[g_off[dst[e]] + g_rank[e]] = src[e];
}

// ---------------- CSR attention: 4 warps/node, fp16 qkv, 4-edge unroll ------------
__global__ void attn_csr_kernel(int M) {
    int gw   = blockIdx.x * (blockDim.x >> 5) + (threadIdx.x >> 5);
    int node = gw >> 2;
    int part = gw & 3;
    int lane = threadIdx.x & 31;
    if (node >= M) return;
    int d0 = g_off[node], d1 = g_off[node + 1];
    int ch = part * 64 + 2 * lane;

    float2 kk = __half22float2(*(const __half2*)(g_qkvh + (size_t)node * QKVW + 256 + ch));
    float k0 = kk.x * SCALE, k1 = kk.y * SCALE;

    float z0 = 0.f, z1 = 0.f, n0 = 0.f, n1 = 0.f;
    int e = d0;
    for (; e + 4 <= d1; e += 4) {
        // batch indices + all loads first (MLP ~9), then arithmetic in edge order
        int s0 = __ldg(&g_ssrc[e + 0]);
        int s1 = __ldg(&g_ssrc[e + 1]);
        int s2 = __ldg(&g_ssrc[e + 2]);
        int s3 = __ldg(&g_ssrc[e + 3]);
        const __half* b0 = g_qkvh + (size_t)s0 * QKVW;
        const __half* b1 = g_qkvh + (size_t)s1 * QKVW;
        const __half* b2 = g_qkvh + (size_t)s2 * QKVW;
        const __half* b3 = g_qkvh + (size_t)s3 * QKVW;
        __half2 q0 = __ldg((const __half2*)(b0 + ch));
        __half2 q1 = __ldg((const __half2*)(b1 + ch));
        __half2 q2 = __ldg((const __half2*)(b2 + ch));
        __half2 q3 = __ldg((const __half2*)(b3 + ch));
        __half2 v0h = __ldg((const __half2*)(b0 + 512 + ch));
        __half2 v1h = __ldg((const __half2*)(b1 + 512 + ch));
        __half2 v2h = __ldg((const __half2*)(b2 + 512 + ch));
        __half2 v3h = __ldg((const __half2*)(b3 + 512 + ch));

        float2 qq, vv;
        float w0, w1;
        qq = __half22float2(q0); vv = __half22float2(v0h);
        w0 = __expf(qq.x * k0); w1 = __expf(qq.y * k1);
        z0 += w0; z1 += w1; n0 += vv.x * w0; n1 += vv.y * w1;
        qq = __half22float2(q1); vv = __half22float2(v1h);
        w0 = __expf(qq.x * k0); w1 = __expf(qq.y * k1);
        z0 += w0; z1 += w1; n0 += vv.x * w0; n1 += vv.y * w1;
        qq = __half22float2(q2); vv = __half22float2(v2h);
        w0 = __expf(qq.x * k0); w1 = __expf(qq.y * k1);
        z0 += w0; z1 += w1; n0 += vv.x * w0; n1 += vv.y * w1;
        qq = __half22float2(q3); vv = __half22float2(v3h);
        w0 = __expf(qq.x * k0); w1 = __expf(qq.y * k1);
        z0 += w0; z1 += w1; n0 += vv.x * w0; n1 += vv.y * w1;
    }
    for (; e < d1; e++) {
        int s = __ldg(&g_ssrc[e]);
        const __half* qb = g_qkvh + (size_t)s * QKVW;
        float2 qq = __half22float2(__ldg((const __half2*)(qb + ch)));
        float2 vv = __half22float2(__ldg((const __half2*)(qb + 512 + ch)));
        float w0 = __expf(qq.x * k0);
        float w1 = __expf(qq.y * k1);
        z0 += w0; z1 += w1;
        n0 += vv.x * w0;
        n1 += vv.y * w1;
    }
    float v0 = (d1 > d0) ? n0 / z0 : 0.f;
    float v1 = (d1 > d0) ? n1 / z1 : 0.f;
    *(__half2*)(g_rsthi + (size_t)node * 256 + ch) = __floats2half2_rn(v0, v1);
}

// ---------------- launch -------------------------------------------------------------
extern "C" void kernel_launch(void* const* d_in, const int* in_sizes, int n_in,
                              void* d_out, int out_size) {
    static cudaStream_t s1 = [] {
        cudaStream_t s; cudaStreamCreateWithFlags(&s, cudaStreamNonBlocking); return s;
    }();
    static cudaStream_t s2 = [] {
        cudaStream_t s; cudaStreamCreateWithFlags(&s, cudaStreamNonBlocking); return s;
    }();
    static cudaEvent_t evF = [] {
        cudaEvent_t e; cudaEventCreateWithFlags(&e, cudaEventDisableTiming); return e;
    }();
    static cudaEvent_t evJ = [] {
        cudaEvent_t e; cudaEventCreateWithFlags(&e, cudaEventDisableTiming); return e;
    }();
    static cudaEvent_t evCsr = [] {
        cudaEvent_t e; cudaEventCreateWithFlags(&e, cudaEventDisableTiming); return e;
    }();
    static cudaEvent_t evW = [] {
        cudaEvent_t e; cudaEventCreateWithFlags(&e, cudaEventDisableTiming); return e;
    }();

    const float* x      = (const float*)d_in[0];
    const float* h      = (const float*)d_in[1];
    const int*   src    = (const int*)  d_in[2];
    const int*   dst    = (const int*)  d_in[3];
    const float* conv_w = (const float*)d_in[4];
    const float* conv_b = (const float*)d_in[5];
    const float* norm_w = (const float*)d_in[6];
    const float* norm_b = (const float*)d_in[7];
    const float* nin_w  = (const float*)d_in[8];
    const float* nin_b  = (const float*)d_in[9];
    const float* w_qkv  = (const float*)d_in[10];
    const float* w_out  = (const float*)d_in[11];
    const float* b_out  = (const float*)d_in[12];
    const float* ffn_w  = (const float*)d_in[13];
    const float* ffn_b  = (const float*)d_in[14];
    const float* w1     = (const float*)d_in[15];
    const float* b1     = (const float*)d_in[16];
    const float* w2     = (const float*)d_in[17];
    const float* b2     = (const float*)d_in[18];
    float* out = (float*)d_out;

    const int M = in_sizes[1] / GDIM;
    const int E = in_sizes[2];

    float *xp, *hn, *attn;
    __half *qkvh, *cwhi, *shi, *qwhi, *rsthi, *owhi, *fhi, *w1hi, *ghi, *w2hi;
    cudaGetSymbolAddress((void**)&xp,    g_xp);
    cudaGetSymbolAddress((void**)&hn,    g_hn);
    cudaGetSymbolAddress((void**)&attn,  g_attn);
    cudaGetSymbolAddress((void**)&qkvh,  g_qkvh);
    cudaGetSymbolAddress((void**)&cwhi,  g_cwhi);
    cudaGetSymbolAddress((void**)&shi,   g_shi);
    cudaGetSymbolAddress((void**)&qwhi,  g_qwhi);
    cudaGetSymbolAddress((void**)&rsthi, g_rsthi);
    cudaGetSymbolAddress((void**)&owhi,  g_owhi);
    cudaGetSymbolAddress((void**)&fhi,   g_fhi);
    cudaGetSymbolAddress((void**)&w1hi,  g_w1hi);
    cudaGetSymbolAddress((void**)&ghi,   g_ghi);
    cudaGetSymbolAddress((void**)&w2hi,  g_w2hi);

    const int SM_FUSE  = 2 * (128 * AFP_ROW + 2 * ARR_BYTES);   // 77824  (NST=2)
    const int SM_PLAIN = 3 * (2 * ARR_BYTES);                   // 61440  (NST=3)
    cudaFuncSetAttribute((const void*)gemm_mma<0, 1, 2>, cudaFuncAttributeMaxDynamicSharedMemorySize, SM_FUSE);
    cudaFuncSetAttribute((const void*)gemm_mma<3, 0, 3>, cudaFuncAttributeMaxDynamicSharedMemorySize, SM_PLAIN);
    cudaFuncSetAttribute((const void*)gemm_mma<0, 0, 3>, cudaFuncAttributeMaxDynamicSharedMemorySize, SM_PLAIN);
    cudaFuncSetAttribute((const void*)gemm_mma<1, 0, 3>, cudaFuncAttributeMaxDynamicSharedMemorySize, SM_PLAIN);
    cudaFuncSetAttribute((const void*)gemm_mma<2, 0, 3>, cudaFuncAttributeMaxDynamicSharedMemorySize, SM_PLAIN);

    const int gy = (M + 127) / 128;

    // ---- fork ----
    cudaEventRecord(evF, 0);
    cudaStreamWaitEvent(s1, evF, 0);
    cudaStreamWaitEvent(s2, evF, 0);

    // ---- stream s1: xproj chain (1-term fp16, 2 CTAs/SM) ----
    {
        int n4 = (GDIM * KBIG) / 4;
        cvt_hi_k<<<(n4 + 255) / 256, 256, 0, s1>>>(conv_w, cwhi, n4);
        gemm_mma<0, 1, 2><<<dim3(GDIM / 128, gy), 256, SM_FUSE, s1>>>(
            x, nullptr, cwhi, conv_b, nullptr, nullptr,
            xp, nullptr, M, GDIM, KBIG);
        cudaEventRecord(evJ, s1);
    }

    // ---- stream s2: CSR build + late-weight converts ----
    {
        zero_deg_kernel<<<(M + 255) / 256, 256, 0, s2>>>(M);
        count_kernel<<<(E + 255) / 256, 256, 0, s2>>>(dst, E);
        scan_kernel<<<1, 1024, 0, s2>>>(M, E);
        scatter_kernel<<<(E + 255) / 256, 256, 0, s2>>>(src, dst, E);
        cudaEventRecord(evCsr, s2);
        int n4 = (GDIM * GDIM) / 4;
        cvt_hi_k<<<(n4 + 255) / 256, 256, 0, s2>>>(w_out, owhi, n4);
        n4 = (HIDDIM * GDIM) / 4;
        cvt_hi_k<<<(n4 + 255) / 256, 256, 0, s2>>>(w1, w1hi, n4);
        n4 = (GDIM * HIDDIM) / 4;
        cvt_hi_k<<<(n4 + 255) / 256, 256, 0, s2>>>(w2, w2hi, n4);
        cudaEventRecord(evW, s2);
    }

    // ---- main stream: attention chain ----
    double_ln_kernel<<<(M + 7) / 8, 256>>>(h, norm_w, norm_b, nin_w, nin_b, hn, shi, M);
    {
        int n4 = (QKVW * GDIM) / 4;
        cvt_hi_k<<<(n4 + 255) / 256, 256>>>(w_qkv, qwhi, n4);
    }
    gemm_mma<3, 0, 3><<<dim3(QKVW / 128, gy), 256, SM_PLAIN>>>(
        nullptr, shi, qwhi, nullptr, nullptr, nullptr,
        nullptr, qkvh, M, QKVW, GDIM);

    cudaStreamWaitEvent(0, evCsr, 0);
    attn_csr_kernel<<<(4 * M + 7) / 8, 256>>>(M);

    cudaStreamWaitEvent(0, evW, 0);
    gemm_mma<0, 0, 3><<<dim3(GDIM / 128, gy), 256, SM_PLAIN>>>(
        nullptr, rsthi, owhi, b_out, nullptr, nullptr,
        attn, nullptr, M, GDIM, GDIM);
    ln_hi_kernel<<<(M + 7) / 8, 256>>>(attn, ffn_w, ffn_b, fhi, M);
    gemm_mma<1, 0, 3><<<dim3(HIDDIM / 128, gy), 256, SM_PLAIN>>>(
        nullptr, fhi, w1hi, b1, nullptr, nullptr,
        nullptr, ghi, M, HIDDIM, GDIM);

    cudaStreamWaitEvent(0, evJ, 0);
    gemm_mma<2, 0, 3><<<dim3(GDIM / 128, gy), 256, SM_PLAIN>>>(
        nullptr, ghi, w2hi, b2, hn, xp,
        out, nullptr, M, GDIM, HIDDIM);
}

// round 16
// speedup vs baseline: 1.0727x; 1.0727x over previous
#include <cuda_runtime.h>
#include <cuda_fp16.h>
#include <math.h>
#include <stdint.h>

// Problem constants
#define NMAX   20000
#define EMAX   320000
#define GDIM   256
#define HIDDIM 512
#define KBIG   4096
#define QKVW   768
#define EPSLN  1e-5f
#define SCALE  0.0625f

// ---------------- scratch (static device globals) ---------------------------
__device__ __align__(256) float g_xp  [NMAX * GDIM];
__device__ __align__(256) float g_hn  [NMAX * GDIM];
__device__ __align__(256) float g_attn[NMAX * GDIM];

__device__ int g_deg [NMAX];
__device__ int g_off [NMAX + 1];
__device__ int g_rank[EMAX];
__device__ int g_ssrc[EMAX];

// fp16 operands
__device__ __align__(256) __half g_qkvh[NMAX * QKVW];
__device__ __align__(256) __half g_cwhi[GDIM * KBIG];
__device__ __align__(256) __half g_shi [NMAX * GDIM];
__device__ __align__(256) __half g_qwhi[QKVW * GDIM];
__device__ __align__(256) __half g_rsthi[NMAX * GDIM];
__device__ __align__(256) __half g_owhi[GDIM * GDIM];
__device__ __align__(256) __half g_fhi [NMAX * GDIM];
__device__ __align__(256) __half g_w1hi[HIDDIM * GDIM];
__device__ __align__(256) __half g_ghi [NMAX * HIDDIM];
__device__ __align__(256) __half g_w2hi[GDIM * HIDDIM];

// ---------------- PTX helpers -------------------------------------------------
__device__ __forceinline__ uint32_t smem_u32(const void* p) {
    uint32_t a;
    asm("{ .reg .u64 t; cvta.to.shared.u64 t, %1; cvt.u32.u64 %0, t; }"
        : "=r"(a) : "l"(p));
    return a;
}
__device__ __forceinline__ void cpasync16(uint32_t dst, const void* src, int bytes) {
    asm volatile("cp.async.cg.shared.global [%0], [%1], 16, %2;"
                 :: "r"(dst), "l"(src), "r"(bytes));
}
__device__ __forceinline__ void cp_commit() { asm volatile("cp.async.commit_group;" ::: "memory"); }

__device__ __forceinline__ void ldm4(uint32_t r[4], uint32_t addr) {
    asm volatile("ldmatrix.sync.aligned.m8n8.x4.shared.b16 {%0,%1,%2,%3}, [%4];"
                 : "=r"(r[0]), "=r"(r[1]), "=r"(r[2]), "=r"(r[3]) : "r"(addr));
}
__device__ __forceinline__ void mma16816(float c[4], const uint32_t a[4], const uint32_t b[2]) {
    asm volatile("mma.sync.aligned.m16n8k16.row.col.f32.f16.f16.f32 "
                 "{%0,%1,%2,%3}, {%4,%5,%6,%7}, {%8,%9}, {%0,%1,%2,%3};"
                 : "+f"(c[0]), "+f"(c[1]), "+f"(c[2]), "+f"(c[3])
                 : "r"(a[0]), "r"(a[1]), "r"(a[2]), "r"(a[3]), "r"(b[0]), "r"(b[1]));
}

// ---------------- 1-term fp16 mma.sync GEMM --------------------------------------
// C[M,Nn] = Ahi[M,K] @ Whi[Nn,K]^T (+bias)(+epilogue); 1 MMA per tile step.
// EPI: 0 = fp32 store, 1 = GELU -> fp16, 2 = +add1+add2 fp32, 3 = plain fp16
// FUSEA: A arrives fp32; loaded via LDG one chunk ahead, converted in regs, STS as half.
#define RSTRIDE   80
#define ARR_BYTES 10240
#define NSTG      3

template <int EPI, int FUSEA>
__global__ void __launch_bounds__(256, 2) gemm_mma(
        const float* __restrict__ Afp,
        const __half* __restrict__ Ahi,
        const __half* __restrict__ Whi,
        const float* __restrict__ bias,
        const float* __restrict__ add1, const float* __restrict__ add2,
        float* __restrict__ Cf, __half* __restrict__ Chi,
        int M, int Nn, int K) {
    constexpr int STB  = 2 * ARR_BYTES;     // per stage: A half tile + W half tile
    constexpr int WOFF = ARR_BYTES;

    extern __shared__ char smem[];
    uint32_t sb = smem_u32(smem);
    const int tid    = threadIdx.x;
    const int wid    = tid >> 5;
    const int lane   = tid & 31;
    const int warp_m = wid & 3;
    const int warp_n = wid >> 2;
    const int bm = blockIdx.y * 128;
    const int bn = blockIdx.x * 128;

    const size_t Krow2 = (size_t)K * 2;

    // x register-pipeline mapping (FUSEA): row = tid>>1, k-half = tid&1
    const int xrow = tid >> 1;
    const int xkh  = tid & 1;
    const bool xok = (bm + xrow) < M;
    const float* xbase = FUSEA ? (Afp + (size_t)(xok ? bm + xrow : 0) * K + xkh * 16) : nullptr;

    auto load_stage = [&](int s, int c) {
        uint32_t base = sb + s * STB;
        size_t kb = (size_t)c * 64;
        if (!FUSEA) {
#pragma unroll
            for (int i = 0; i < 2; i++) {
                int u = tid + i * 256;
                int row = u >> 2, seg = u & 3;
                uint32_t so = (uint32_t)(row * RSTRIDE + seg * 16);
                int ga = bm + row;
                bool ok = ga < M;
                size_t go = (size_t)(ok ? ga : 0) * Krow2 + kb + seg * 16;
                cpasync16(base + so, (const char*)Ahi + go, ok ? 16 : 0);
            }
        }
#pragma unroll
        for (int i = 0; i < 2; i++) {
            int u = tid + i * 256;
            int row = u >> 2, seg = u & 3;
            uint32_t so = (uint32_t)(row * RSTRIDE + seg * 16);
            size_t gw = (size_t)(bn + row) * Krow2 + kb + seg * 16;
            cpasync16(base + WOFF + so, (const char*)Whi + gw, 16);
        }
        cp_commit();
    };

    const int nc = K >> 5;

    float4 f4n[4];
    uint32_t h2cur[8];
    auto ldx = [&](int c) {
#pragma unroll
        for (int q = 0; q < 4; q++)
            f4n[q] = xok ? *(const float4*)(xbase + (size_t)c * 32 + q * 4)
                         : make_float4(0.f, 0.f, 0.f, 0.f);
    };
    auto cvtx = [&]() {
#pragma unroll
        for (int q = 0; q < 4; q++) {
            __half2 a = __floats2half2_rn(f4n[q].x, f4n[q].y);
            __half2 b = __floats2half2_rn(f4n[q].z, f4n[q].w);
            h2cur[2 * q]     = *(uint32_t*)&a;
            h2cur[2 * q + 1] = *(uint32_t*)&b;
        }
    };

    if (FUSEA) ldx(0);
#pragma unroll
    for (int s = 0; s < NSTG; s++) load_stage(s, s);
    if (FUSEA) cvtx();

    float acc[2][8][4];
#pragma unroll
    for (int i = 0; i < 2; i++)
#pragma unroll
        for (int j = 0; j < 8; j++)
#pragma unroll
            for (int q = 0; q < 4; q++) acc[i][j][q] = 0.f;

    for (int c = 0; c < nc; c++) {
        int s = c % NSTG;
        if (FUSEA && c + 1 < nc) ldx(c + 1);
        int allow = min(nc, c + NSTG) - c - 1;
        if (allow >= 2)      asm volatile("cp.async.wait_group 2;" ::: "memory");
        else if (allow == 1) asm volatile("cp.async.wait_group 1;" ::: "memory");
        else                 asm volatile("cp.async.wait_group 0;" ::: "memory");
        __syncthreads();

        if (FUSEA) {
            char* ab = smem + s * STB + xrow * RSTRIDE + xkh * 32;
#pragma unroll
            for (int q = 0; q < 4; q++)
                *(uint2*)(ab + q * 8) = make_uint2(h2cur[2 * q], h2cur[2 * q + 1]);
            __syncthreads();
        }

        uint32_t AB = sb + s * STB;
#pragma unroll
        for (int ks = 0; ks < 2; ks++) {
            uint32_t a_hi[2][4];
#pragma unroll
            for (int fm = 0; fm < 2; fm++) {
                uint32_t ar = AB + (uint32_t)((warp_m * 32 + fm * 16 + (lane & 15)) * RSTRIDE)
                              + ks * 32 + ((lane >> 4) << 4);
                ldm4(a_hi[fm], ar);
            }
            uint32_t b_hi[8][2];
#pragma unroll
            for (int fp = 0; fp < 4; fp++) {
                uint32_t br = AB + WOFF
                              + (uint32_t)((warp_n * 64 + fp * 16 + ((lane >> 4) << 3) + (lane & 7)) * RSTRIDE)
                              + ks * 32 + (((lane >> 3) & 1) << 4);
                uint32_t t[4];
                ldm4(t, br);
                b_hi[2 * fp][0] = t[0]; b_hi[2 * fp][1] = t[1];
                b_hi[2 * fp + 1][0] = t[2]; b_hi[2 * fp + 1][1] = t[3];
            }
#pragma unroll
            for (int fm = 0; fm < 2; fm++)
#pragma unroll
                for (int fn = 0; fn < 8; fn++)
                    mma16816(acc[fm][fn], a_hi[fm], b_hi[fn]);
        }
        __syncthreads();
        if (c + NSTG < nc) load_stage(s, c + NSTG);
        if (FUSEA && c + 1 < nc) cvtx();
    }

    // epilogue
#pragma unroll
    for (int fm = 0; fm < 2; fm++) {
        int r0 = bm + warp_m * 32 + fm * 16 + (lane >> 2);
#pragma unroll
        for (int half = 0; half < 2; half++) {
            int row = r0 + half * 8;
            if (row >= M) continue;
#pragma unroll
            for (int fn = 0; fn < 8; fn++) {
                int col = bn + warp_n * 64 + fn * 8 + (lane & 3) * 2;
                float v0 = acc[fm][fn][half * 2 + 0];
                float v1 = acc[fm][fn][half * 2 + 1];
                if (bias) { v0 += bias[col]; v1 += bias[col + 1]; }
                size_t ob = (size_t)row * Nn + col;
                if (EPI == 0) {
                    *(float2*)(Cf + ob) = make_float2(v0, v1);
                } else if (EPI == 1) {
                    float u0 = 0.5f * v0 * (1.0f + erff(v0 * 0.70710678118654752f));
                    float u1 = 0.5f * v1 * (1.0f + erff(v1 * 0.70710678118654752f));
                    *(__half2*)(Chi + ob) = __floats2half2_rn(u0, u1);
                } else if (EPI == 2) {
                    float2 a1 = *(const float2*)(add1 + ob);
                    float2 a2 = *(const float2*)(add2 + ob);
                    *(float2*)(Cf + ob) = make_float2(v0 + a1.x + a2.x, v1 + a1.y + a2.y);
                } else {
                    *(__half2*)(Chi + ob) = __floats2half2_rn(v0, v1);
                }
            }
        }
    }
}

// ---------------- fp32 -> fp16 convert --------------------------------------------
__global__ void cvt_hi_k(const float* __restrict__ src, __half* __restrict__ hi, int n4) {
    int i = blockIdx.x * blockDim.x + threadIdx.x;
    if (i >= n4) return;
    float4 v = ((const float4*)src)[i];
    ((__half2*)hi)[2 * i]     = __floats2half2_rn(v.x, v.y);
    ((__half2*)hi)[2 * i + 1] = __floats2half2_rn(v.z, v.w);
}

// ---------------- LayerNorm helpers ---------------------------------------------
__device__ __forceinline__ float wredsum(float v) {
#pragma unroll
    for (int o = 16; o > 0; o >>= 1) v += __shfl_xor_sync(0xffffffffu, v, o);
    return v;
}
__device__ __forceinline__ void ln_row(float v[8], int lane,
                                       const float* __restrict__ w,
                                       const float* __restrict__ b, float o[8]) {
    float sum = 0.f;
#pragma unroll
    for (int j = 0; j < 8; j++) sum += v[j];
    sum = wredsum(sum);
    float mu = sum * (1.0f / 256.0f);
    float sq = 0.f;
#pragma unroll
    for (int j = 0; j < 8; j++) { float d = v[j] - mu; sq += d * d; }
    sq = wredsum(sq);
    float rs = rsqrtf(sq * (1.0f / 256.0f) + EPSLN);
#pragma unroll
    for (int j = 0; j < 8; j++) {
        int i = lane + 32 * j;
        o[j] = (v[j] - mu) * rs * w[i] + b[i];
    }
}

__global__ void double_ln_kernel(const float* __restrict__ h,
                                 const float* __restrict__ nw, const float* __restrict__ nb,
                                 const float* __restrict__ iw, const float* __restrict__ ib,
                                 float* __restrict__ hn,
                                 __half* __restrict__ shi, int M) {
    int row  = blockIdx.x * (blockDim.x >> 5) + (threadIdx.x >> 5);
    int lane = threadIdx.x & 31;
    if (row >= M) return;
    const float* r = h + (size_t)row * 256;
    float v[8], o1[8], o2[8];
#pragma unroll
    for (int j = 0; j < 8; j++) v[j] = r[lane + 32 * j];
    ln_row(v, lane, nw, nb, o1);
#pragma unroll
    for (int j = 0; j < 8; j++) hn[(size_t)row * 256 + lane + 32 * j] = o1[j];
    ln_row(o1, lane, iw, ib, o2);
#pragma unroll
    for (int j = 0; j < 8; j++)
        shi[(size_t)row * 256 + lane + 32 * j] = __float2half_rn(o2[j]);
}

__global__ void ln_hi_kernel(const float* __restrict__ in,
                             const float* __restrict__ w, const float* __restrict__ b,
                             __half* __restrict__ fhi, int M) {
    int row  = blockIdx.x * (blockDim.x >> 5) + (threadIdx.x >> 5);
    int lane = threadIdx.x & 31;
    if (row >= M) return;
    const float* r = in + (size_t)row * 256;
    float v[8], o[8];
#pragma unroll
    for (int j = 0; j < 8; j++) v[j] = r[lane + 32 * j];
    ln_row(v, lane, w, b, o);
#pragma unroll
    for (int j = 0; j < 8; j++)
        fhi[(size_t)row * 256 + lane + 32 * j] = __float2half_rn(o[j]);
}

// ---------------- CSR build ------------------------------------------------------
__global__ void zero_deg_kernel(int M) {
    int i = blockIdx.x * blockDim.x + threadIdx.x;
    if (i < M) g_deg[i] = 0;
}
__global__ void count_kernel(const int* __restrict__ dst, int E) {
    int e = blockIdx.x * blockDim.x + threadIdx.x;
    if (e >= E) return;
    g_rank[e] = atomicAdd(&g_deg[dst[e]], 1);
}
__global__ void scan_kernel(int M, int E) {
    __shared__ int a[1024], b[1024];
    __shared__ int carry;
    int tid = threadIdx.x;
    if (tid == 0) carry = 0;
    __syncthreads();
    for (int base = 0; base < M; base += 1024) {
        int i = base + tid;
        int v = (i < M) ? g_deg[i] : 0;
        a[tid] = v;
        __syncthreads();
        int* s = a; int* d = b;
#pragma unroll
        for (int o = 1; o < 1024; o <<= 1) {
            int t = s[tid] + ((tid >= o) ? s[tid - o] : 0);
            d[tid] = t;
            __syncthreads();
            int* tmp = s; s = d; d = tmp;
        }
        if (i < M) g_off[i] = carry + s[tid] - v;
        int total = s[1023];
        __syncthreads();
        if (tid == 0) carry += total;
        __syncthreads();
    }
    if (tid == 0) g_off[M] = E;
}
__global__ void scatter_kernel(const int* __restrict__ src, const int* __restrict__ dst, int E) {
    int e = blockIdx.x * blockDim.x + threadIdx.x;
    if (e >= E) return;
    g_ssrc[g_off[dst[e]] + g_rank[e]] = src[e];
}

// ---------------- CSR attention: 4 warps/node, fp16 qkv ---------------------------
__global__ void attn_csr_kernel(int M) {
    int gw   = blockIdx.x * (blockDim.x >> 5) + (threadIdx.x >> 5);
    int node = gw >> 2;
    int part = gw & 3;
    int lane = threadIdx.x & 31;
    if (node >= M) return;
    int d0 = g_off[node], d1 = g_off[node + 1];
    int ch = part * 64 + 2 * lane;

    float2 kk = __half22float2(*(const __half2*)(g_qkvh + (size_t)node * QKVW + 256 + ch));
    float k0 = kk.x * SCALE, k1 = kk.y * SCALE;

    float z0 = 0.f, z1 = 0.f, n0 = 0.f, n1 = 0.f;
    for (int e = d0; e < d1; e++) {
        int s = g_ssrc[e];
        const __half* qb = g_qkvh + (size_t)s * QKVW;
        float2 qq = __half22float2(*(const __half2*)(qb + ch));
        float2 vv = __half22float2(*(const __half2*)(qb + 512 + ch));
        float w0 = __expf(qq.x * k0);
        float w1 = __expf(qq.y * k1);
        z0 += w0; z1 += w1;
        n0 += vv.x * w0;
        n1 += vv.y * w1;
    }
    float v0 = (d1 > d0) ? n0 / z0 : 0.f;
    float v1 = (d1 > d0) ? n1 / z1 : 0.f;
    *(__half2*)(g_rsthi + (size_t)node * 256 + ch) = __floats2half2_rn(v0, v1);
}

// ---------------- launch -------------------------------------------------------------
extern "C" void kernel_launch(void* const* d_in, const int* in_sizes, int n_in,
                              void* d_out, int out_size) {
    static cudaStream_t s1 = [] {
        int lo, hi;
        cudaDeviceGetStreamPriorityRange(&lo, &hi);   // hi = highest priority (most negative)
        cudaStream_t s;
        cudaStreamCreateWithPriority(&s, cudaStreamNonBlocking, hi);
        return s;
    }();
    static cudaStream_t s2 = [] {
        cudaStream_t s; cudaStreamCreateWithFlags(&s, cudaStreamNonBlocking); return s;
    }();
    static cudaEvent_t evF = [] {
        cudaEvent_t e; cudaEventCreateWithFlags(&e, cudaEventDisableTiming); return e;
    }();
    static cudaEvent_t evJ = [] {
        cudaEvent_t e; cudaEventCreateWithFlags(&e, cudaEventDisableTiming); return e;
    }();
    static cudaEvent_t evCsr = [] {
        cudaEvent_t e; cudaEventCreateWithFlags(&e, cudaEventDisableTiming); return e;
    }();
    static cudaEvent_t evW = [] {
        cudaEvent_t e; cudaEventCreateWithFlags(&e, cudaEventDisableTiming); return e;
    }();

    const float* x      = (const float*)d_in[0];
    const float* h      = (const float*)d_in[1];
    const int*   src    = (const int*)  d_in[2];
    const int*   dst    = (const int*)  d_in[3];
    const float* conv_w = (const float*)d_in[4];
    const float* conv_b = (const float*)d_in[5];
    const float* norm_w = (const float*)d_in[6];
    const float* norm_b = (const float*)d_in[7];
    const float* nin_w  = (const float*)d_in[8];
    const float* nin_b  = (const float*)d_in[9];
    const float* w_qkv  = (const float*)d_in[10];
    const float* w_out  = (const float*)d_in[11];
    const float* b_out  = (const float*)d_in[12];
    const float* ffn_w  = (const float*)d_in[13];
    const float* ffn_b  = (const float*)d_in[14];
    const float* w1     = (const float*)d_in[15];
    const float* b1     = (const float*)d_in[16];
    const float* w2     = (const float*)d_in[17];
    const float* b2     = (const float*)d_in[18];
    float* out = (float*)d_out;

    const int M = in_sizes[1] / GDIM;
    const int E = in_sizes[2];

    float *xp, *hn, *attn;
    __half *qkvh, *cwhi, *shi, *qwhi, *rsthi, *owhi, *fhi, *w1hi, *ghi, *w2hi;
    cudaGetSymbolAddress((void**)&xp,    g_xp);
    cudaGetSymbolAddress((void**)&hn,    g_hn);
    cudaGetSymbolAddress((void**)&attn,  g_attn);
    cudaGetSymbolAddress((void**)&qkvh,  g_qkvh);
    cudaGetSymbolAddress((void**)&cwhi,  g_cwhi);
    cudaGetSymbolAddress((void**)&shi,   g_shi);
    cudaGetSymbolAddress((void**)&qwhi,  g_qwhi);
    cudaGetSymbolAddress((void**)&rsthi, g_rsthi);
    cudaGetSymbolAddress((void**)&owhi,  g_owhi);
    cudaGetSymbolAddress((void**)&fhi,   g_fhi);
    cudaGetSymbolAddress((void**)&w1hi,  g_w1hi);
    cudaGetSymbolAddress((void**)&ghi,   g_ghi);
    cudaGetSymbolAddress((void**)&w2hi,  g_w2hi);

    const int SM_GEMM = NSTG * (2 * ARR_BYTES);   // 61440 for all variants
    cudaFuncSetAttribute((const void*)gemm_mma<0, 1>, cudaFuncAttributeMaxDynamicSharedMemorySize, SM_GEMM);
    cudaFuncSetAttribute((const void*)gemm_mma<3, 0>, cudaFuncAttributeMaxDynamicSharedMemorySize, SM_GEMM);
    cudaFuncSetAttribute((const void*)gemm_mma<0, 0>, cudaFuncAttributeMaxDynamicSharedMemorySize, SM_GEMM);
    cudaFuncSetAttribute((const void*)gemm_mma<1, 0>, cudaFuncAttributeMaxDynamicSharedMemorySize, SM_GEMM);
    cudaFuncSetAttribute((const void*)gemm_mma<2, 0>, cudaFuncAttributeMaxDynamicSharedMemorySize, SM_GEMM);

    const int gy = (M + 127) / 128;

    // ---- fork ----
    cudaEventRecord(evF, 0);
    cudaStreamWaitEvent(s1, evF, 0);
    cudaStreamWaitEvent(s2, evF, 0);

    // ---- stream s1 (high priority): xproj chain ----
    {
        int n4 = (GDIM * KBIG) / 4;
        cvt_hi_k<<<(n4 + 255) / 256, 256, 0, s1>>>(conv_w, cwhi, n4);
        gemm_mma<0, 1><<<dim3(GDIM / 128, gy), 256, SM_GEMM, s1>>>(
            x, nullptr, cwhi, conv_b, nullptr, nullptr,
            xp, nullptr, M, GDIM, KBIG);
        cudaEventRecord(evJ, s1);
    }

    // ---- stream s2: CSR build + late-weight converts ----
    {
        zero_deg_kernel<<<(M + 255) / 256, 256, 0, s2>>>(M);
        count_kernel<<<(E + 255) / 256, 256, 0, s2>>>(dst, E);
        scan_kernel<<<1, 1024, 0, s2>>>(M, E);
        scatter_kernel<<<(E + 255) / 256, 256, 0, s2>>>(src, dst, E);
        cudaEventRecord(evCsr, s2);
        int n4 = (GDIM * GDIM) / 4;
        cvt_hi_k<<<(n4 + 255) / 256, 256, 0, s2>>>(w_out, owhi, n4);
        n4 = (HIDDIM * GDIM) / 4;
        cvt_hi_k<<<(n4 + 255) / 256, 256, 0, s2>>>(w1, w1hi, n4);
        n4 = (GDIM * HIDDIM) / 4;
        cvt_hi_k<<<(n4 + 255) / 256, 256, 0, s2>>>(w2, w2hi, n4);
        cudaEventRecord(evW, s2);
    }

    // ---- main stream: attention chain ----
    double_ln_kernel<<<(M + 7) / 8, 256>>>(h, norm_w, norm_b, nin_w, nin_b, hn, shi, M);
    {
        int n4 = (QKVW * GDIM) / 4;
        cvt_hi_k<<<(n4 + 255) / 256, 256>>>(w_qkv, qwhi, n4);
    }
    gemm_mma<3, 0><<<dim3(QKVW / 128, gy), 256, SM_GEMM>>>(
        nullptr, shi, qwhi, nullptr, nullptr, nullptr,
        nullptr, qkvh, M, QKVW, GDIM);

    cudaStreamWaitEvent(0, evCsr, 0);
    attn_csr_kernel<<<(4 * M + 7) / 8, 256>>>(M);

    cudaStreamWaitEvent(0, evW, 0);
    gemm_mma<0, 0><<<dim3(GDIM / 128, gy), 256, SM_GEMM>>>(
        nullptr, rsthi, owhi, b_out, nullptr, nullptr,
        attn, nullptr, M, GDIM, GDIM);
    ln_hi_kernel<<<(M + 7) / 8, 256>>>(attn, ffn_w, ffn_b, fhi, M);
    gemm_mma<1, 0><<<dim3(HIDDIM / 128, gy), 256, SM_GEMM>>>(
        nullptr, fhi, w1hi, b1, nullptr, nullptr,
        nullptr, ghi, M, HIDDIM, GDIM);

    cudaStreamWaitEvent(0, evJ, 0);
    gemm_mma<2, 0><<<dim3(GDIM / 128, gy), 256, SM_GEMM>>>(
        nullptr, ghi, w2hi, b2, hn, xp,
        out, nullptr, M, GDIM, HIDDIM);
}